// round 10
// baseline (speedup 1.0000x reference)
#include <cuda_runtime.h>
#include <cstdint>
#include <cstddef>

// out[b,i,j,c] = (gelu(pos_table[max(i-j,0)] @ W1 + b1) @ W2 + b2)[c]
// T=512, E=64, H=128. Only 512 distinct rows -> build 512x128 table, scatter.
//
// R10 = R9 with the fill-indexing bug fixed (idx stride was 512 with 256
// threads -> SMEM OOB; must be u*256+tid covering exactly 1024 float4).
// Hypothesis under test: the async bulk-copy write path (UBLKCP, 16 KB
// SMEM->GMEM bursts) sustains more DRAM write BW than the STG path's
// ~5.3 TB/s, which is the measured replay-period floor (268 MB/replay).

#define T_DIM 512
#define E_DIM 64
#define H_DIM 128

#define STAGE_F4 1024            // 16 KB per stage
#define N_STAGES 16              // 16 x 16 KB = 256 KB = one (b,i) row
#define SCATTER_THREADS 256

__device__ float g_table[T_DIM * H_DIM];   // 256 KB scratch (static, no alloc)

__device__ __forceinline__ uint32_t smem_u32(const void* p) {
    uint32_t a;
    asm("{ .reg .u64 t; cvta.to.shared.u64 t, %1; cvt.u32.u64 %0, t; }"
        : "=r"(a) : "l"(p));
    return a;
}

// ---------------------------------------------------------------------------
// Kernel A: build the table (512 blocks x 128 threads; best measured shape).
// ---------------------------------------------------------------------------
__global__ void __launch_bounds__(H_DIM)
build_table_kernel(const float* __restrict__ pos_table,
                   const float* __restrict__ W1,
                   const float* __restrict__ b1,
                   const float* __restrict__ W2,
                   const float* __restrict__ b2) {
    __shared__ float sp[E_DIM];
    __shared__ float sh[H_DIM];

    const int d = blockIdx.x;      // distance row 0..511
    const int j = threadIdx.x;     // output column 0..127

    if (j < E_DIM) sp[j] = pos_table[d * E_DIM + j];
    __syncthreads();

    float acc = b1[j];
#pragma unroll
    for (int k = 0; k < E_DIM; k++)
        acc = fmaf(sp[k], W1[k * H_DIM + j], acc);
    // Exact GELU: 0.5*x*(1+erf(x/sqrt(2)))
    sh[j] = 0.5f * acc * (1.0f + erff(acc * 0.70710678118654752f));
    __syncthreads();

    float acc2 = b2[j];
#pragma unroll
    for (int k = 0; k < H_DIM; k++)
        acc2 = fmaf(sh[k], W2[k * H_DIM + j], acc2);

    g_table[d * H_DIM + j] = acc2;
}

// ---------------------------------------------------------------------------
// Kernel B: bulk-store scatter.
// Block = (b, i): one 256 KB output row out[b,i,:,:] in 16 stages of 16 KB,
// double-buffered (32 KB smem -> 7 blocks/SM, grid 1024 ~= one wave).
// Stage s covers j in [32s, 32s+32).
// Fill: idx = u*256 + tid (exactly 1024 float4): c = idx&31 (lane),
//   jl = idx>>5 (warp-uniform 0..31) -> coalesced 512 B table read per warp,
//   conflict-free SMEM write.
// Drain: per-thread async-proxy fence, then tid0 issues a 16 KB
//   cp.async.bulk + commit_group; wait_group 1 keeps 2 stages in flight.
// ---------------------------------------------------------------------------
__global__ void __launch_bounds__(SCATTER_THREADS)
scatter_kernel(float4* __restrict__ out) {
    __shared__ alignas(128) float4 buf[2][STAGE_F4];

    const int i = blockIdx.x & (T_DIM - 1);
    const int b = blockIdx.x >> 9;
    const int tid = threadIdx.x;

    const float4* __restrict__ tbl = reinterpret_cast<const float4*>(g_table);
    float4* const row_base = out + (((size_t)b * T_DIM + i) * T_DIM) * (H_DIM / 4);

    for (int s = 0; s < N_STAGES; s++) {
        float4* sb = buf[s & 1];

        // Throttle: this buffer's previous bulk store (stage s-2) must have
        // been consumed before refill. wait_group 1 allows stage s-1 to
        // remain in flight.
        if (tid == 0 && s >= 2) {
            asm volatile("cp.async.bulk.wait_group 1;" ::: "memory");
        }
        __syncthreads();

        // Fill exactly 16 KB: 4 float4 per thread.
        const int j_base = s << 5;                    // 32 j per stage
#pragma unroll
        for (int u = 0; u < 4; u++) {
            const int idx = (u << 8) + tid;           // 0..1023
            const int c   = idx & 31;                 // lane
            const int jl  = idx >> 5;                 // 0..31, warp-uniform
            const int j   = j_base + jl;
            const int d   = i - j;
            const int row = d > 0 ? d : 0;
            sb[idx] = __ldg(tbl + row * (H_DIM / 4) + c);
        }
        // Make generic-proxy SMEM writes visible to the async proxy
        // (per-thread fence BEFORE the barrier, CUTLASS ordering).
        asm volatile("fence.proxy.async.shared::cta;" ::: "memory");
        __syncthreads();

        if (tid == 0) {
            const uint32_t src = smem_u32(sb);
            float4* dst = row_base + (size_t)j_base * (H_DIM / 4);
            asm volatile(
                "cp.async.bulk.global.shared::cta.bulk_group [%0], [%1], %2;"
                :: "l"(dst), "r"(src), "r"((uint32_t)(STAGE_F4 * 16))
                : "memory");
            asm volatile("cp.async.bulk.commit_group;" ::: "memory");
        }
    }

    // Drain remaining bulk ops before the CTA (and its SMEM) retires.
    if (tid == 0) {
        asm volatile("cp.async.bulk.wait_group 0;" ::: "memory");
    }
    __syncthreads();
}

extern "C" void kernel_launch(void* const* d_in, const int* in_sizes, int n_in,
                              void* d_out, int out_size) {
    // Inputs: b, pos_table, W1, b1, W2, b2 (scalar b may or may not be input 0).
    int base = 0;
    if (n_in >= 6) {
        base = 1;
    } else if (n_in == 5 && in_sizes[0] == T_DIM * E_DIM) {
        base = 0;
    }
    const float* pos_table = (const float*)d_in[base + 0];
    const float* W1        = (const float*)d_in[base + 1];
    const float* b1        = (const float*)d_in[base + 2];
    const float* W2        = (const float*)d_in[base + 3];
    const float* b2        = (const float*)d_in[base + 4];

    const int bsz = out_size / (T_DIM * T_DIM * H_DIM);

    build_table_kernel<<<T_DIM, H_DIM>>>(pos_table, W1, b1, W2, b2);

    scatter_kernel<<<T_DIM * bsz, SCATTER_THREADS>>>((float4*)d_out);
}

// round 11
// speedup vs baseline: 1.1611x; 1.1611x over previous
#include <cuda_runtime.h>
#include <cstdint>
#include <cstddef>

// out[b,i,j,c] = (gelu(pos_table[max(i-j,0)] @ W1 + b1) @ W2 + b2)[c]
// T=512, E=64, H=128. Only 512 distinct rows -> build 512x128 table, scatter.
//
// R11 model (R1-R10 measured): replay period = 268 MB mandatory DRAM writes /
// ~5.3 TB/s = 50.6us floor; grid shape, waves, verify-reads, mixed traffic,
// and the bulk-copy engine are all confirmed non-levers. Untested lever:
// WRITEBACK ORDER. Dirty-line eviction drains in LRU/hash order (page-
// hostile). st.global.wt drains in store order (per-channel near-sequential
// -> DRAM page hits). Keep the measured-good evict_last 112 MB prefix
// (R5: +1.4us from L2 retention), write-through the 156 MB remainder.

#define T_DIM 512
#define E_DIM 64
#define H_DIM 128

// Biased-resident region: 112 MB = 7,340,032 float4 = 896 scatter blocks.
#define P_F4 7340032ull

__device__ float g_table[T_DIM * H_DIM];   // 256 KB scratch (static, no alloc)

__device__ __forceinline__ uint64_t make_evict_last_policy() {
    uint64_t pol;
    asm("createpolicy.fractional.L2::evict_last.b64 %0, 1.0;" : "=l"(pol));
    return pol;
}

__device__ __forceinline__ void st_pinned(float4* p, float4 v, uint64_t pol) {
    asm volatile(
        "st.global.L2::cache_hint.v4.f32 [%0], {%1,%2,%3,%4}, %5;"
        :: "l"(p), "f"(v.x), "f"(v.y), "f"(v.z), "f"(v.w), "l"(pol)
        : "memory");
}

// Write-through: line goes to the DRAM write queue immediately, in store
// order (per-channel near-sequential addresses -> page-hit-friendly bursts).
__device__ __forceinline__ void st_wt(float4* p, float4 v) {
    asm volatile(
        "st.global.wt.v4.f32 [%0], {%1,%2,%3,%4};"
        :: "l"(p), "f"(v.x), "f"(v.y), "f"(v.z), "f"(v.w)
        : "memory");
}

// ---------------------------------------------------------------------------
// Kernel A: build the table (512 blocks x 128 threads; best measured shape).
// Table stored evict_last so the scatter's gather reads stay L2-resident.
// ---------------------------------------------------------------------------
__global__ void __launch_bounds__(H_DIM)
build_table_kernel(const float* __restrict__ pos_table,
                   const float* __restrict__ W1,
                   const float* __restrict__ b1,
                   const float* __restrict__ W2,
                   const float* __restrict__ b2) {
    __shared__ float sp[E_DIM];
    __shared__ float sh[H_DIM];

    const int d = blockIdx.x;      // distance row 0..511
    const int j = threadIdx.x;     // output column 0..127

    if (j < E_DIM) sp[j] = pos_table[d * E_DIM + j];
    __syncthreads();

    float acc = b1[j];
#pragma unroll
    for (int k = 0; k < E_DIM; k++)
        acc = fmaf(sp[k], W1[k * H_DIM + j], acc);
    // Exact GELU: 0.5*x*(1+erf(x/sqrt(2)))
    sh[j] = 0.5f * acc * (1.0f + erff(acc * 0.70710678118654752f));
    __syncthreads();

    float acc2 = b2[j];
#pragma unroll
    for (int k = 0; k < H_DIM; k++)
        acc2 = fmaf(sh[k], W2[k * H_DIM + j], acc2);

    const uint64_t pol = make_evict_last_policy();
    asm volatile("st.global.L2::cache_hint.f32 [%0], %1, %2;"
                 :: "l"(&g_table[d * H_DIM + j]), "f"(acc2), "l"(pol)
                 : "memory");
}

// ---------------------------------------------------------------------------
// Kernel B: row-contiguous scatter, split write policy.
// Block = (half, i, b): 128 KB contiguous span of the output.
// Linear offsets < 112 MB -> evict_last stores (measured L2-retention win);
// rest -> write-through stores (store-order drain, DRAM page locality).
// ---------------------------------------------------------------------------
__global__ void __launch_bounds__(256)
scatter_kernel(float4* __restrict__ out) {
    const int i    = blockIdx.y;
    const int b    = blockIdx.z;
    const int j0   = blockIdx.x << 8;    // 0 or 256
    const int warp = threadIdx.x >> 5;   // 0..7
    const int lane = threadIdx.x & 31;

    const float4* __restrict__ tbl = reinterpret_cast<const float4*>(g_table);
    float4* __restrict__ dst =
        out + (((size_t)b * T_DIM + i) * T_DIM) * (H_DIM / 4) + lane;

    const int jw = j0 + (warp << 5);     // this warp's 32-j contiguous span

    // Block's starting float4 offset; each block covers 8192 float4.
    const size_t base_f4 = (((size_t)b * T_DIM + i) * T_DIM + j0) * (H_DIM / 4);
    const bool pinned = (base_f4 + 8192ull) <= P_F4;

    if (pinned) {
        const uint64_t pol = make_evict_last_policy();
#pragma unroll 4
        for (int t = 0; t < 32; t++) {
            const int j   = jw + t;
            const int d   = i - j;
            const int row = d > 0 ? d : 0;
            const float4 v = __ldg(tbl + row * (H_DIM / 4) + lane);
            st_pinned(dst + (size_t)j * (H_DIM / 4), v, pol);
        }
    } else {
#pragma unroll 4
        for (int t = 0; t < 32; t++) {
            const int j   = jw + t;
            const int d   = i - j;
            const int row = d > 0 ? d : 0;
            const float4 v = __ldg(tbl + row * (H_DIM / 4) + lane);
            st_wt(dst + (size_t)j * (H_DIM / 4), v);
        }
    }
}

extern "C" void kernel_launch(void* const* d_in, const int* in_sizes, int n_in,
                              void* d_out, int out_size) {
    // Inputs: b, pos_table, W1, b1, W2, b2 (scalar b may or may not be input 0).
    int base = 0;
    if (n_in >= 6) {
        base = 1;
    } else if (n_in == 5 && in_sizes[0] == T_DIM * E_DIM) {
        base = 0;
    }
    const float* pos_table = (const float*)d_in[base + 0];
    const float* W1        = (const float*)d_in[base + 1];
    const float* b1        = (const float*)d_in[base + 2];
    const float* W2        = (const float*)d_in[base + 3];
    const float* b2        = (const float*)d_in[base + 4];

    const int bsz = out_size / (T_DIM * T_DIM * H_DIM);

    build_table_kernel<<<T_DIM, H_DIM>>>(pos_table, W1, b1, W2, b2);

    dim3 grid(2, T_DIM, bsz);            // 2 half-rows x 512 i x batch
    scatter_kernel<<<grid, 256>>>((float4*)d_out);
}